// round 7
// baseline (speedup 1.0000x reference)
#include <cuda_runtime.h>

#define BN_EPS 1e-5f

typedef unsigned long long ull;
typedef long long ll;

// Deterministic BN partial-stat scratch: [row-half][global L0 feature]
__device__ float g_ssum[2][65536];
__device__ float g_ssq[2][65536];

__device__ __forceinline__ ull pack2(float lo, float hi) {
    ull r; asm("mov.b64 %0, {%1, %2};" : "=l"(r) : "f"(lo), "f"(hi)); return r;
}
__device__ __forceinline__ void unpack2(ull v, float& lo, float& hi) {
    asm("mov.b64 {%0, %1}, %2;" : "=f"(lo), "=f"(hi) : "l"(v));
}
__device__ __forceinline__ ull fma2(ull a, ull b, ull c) {
    ull d; asm("fma.rn.f32x2 %0, %1, %2, %3;" : "=l"(d) : "l"(a), "l"(b), "l"(c)); return d;
}
// accurate tanh (~1e-7 rel)
__device__ __forceinline__ float ftanh(float x) {
    float e = __expf(2.0f * x);
    return 1.0f - __fdividef(2.0f, e + 1.0f);
}
// XOR-swizzled float4-column index for a [rows][16]-float smem tile
__device__ __forceinline__ int swz(int row, int part) {
    return row * 16 + (((part + (row >> 1)) & 3) << 2);
}

// ===================== Kernel A: L0 GEMM + tanh + partial stats =====================
// Block = 2 terms x 1024 rows (half batch). 256 threads, 4 rows/thread.
// Writes RAW tanh activations into the t0 output region; BN partials to scratch.
#define TA 256
#define NWA 8

__global__ void __launch_bounds__(TA, 2)
l0_gemm(const float* __restrict__ x,
        const float* __restrict__ W0, const float* __restrict__ b0,
        float* __restrict__ out_t)
{
    extern __shared__ float sm[];
    float* sh_x = sm;              // [1024*16] swizzled; reused as store tile
    float* sh_w = sm + 1024 * 16;  // [1024]
    float* sb0  = sh_w + 1024;     // [16]
    float* red  = sb0 + 16;        // [16*NWA*2]

    const int tid  = threadIdx.x;
    const int lane = tid & 31;
    const int warp = tid >> 5;
    const int tt   = blockIdx.x >> 1;   // term-pair index
    const int rt   = blockIdx.x & 1;    // row half
    const int m0   = tt * 2;
    const int r0   = rt * 1024;

    for (int i = tid; i < 1024; i += TA) sh_w[i] = W0[(ll)m0 * 512 + i];
    if (tid < 16) sb0[tid] = b0[m0 * 8 + tid];

    ull acc[4][8];
    #pragma unroll
    for (int r = 0; r < 4; ++r)
        #pragma unroll
        for (int j = 0; j < 8; ++j) acc[r][j] = 0ull;

    const ulonglong2* shw2 = reinterpret_cast<const ulonglong2*>(sh_w);

    #pragma unroll 1
    for (int c = 0; c < 4; ++c) {
        __syncthreads();
        #pragma unroll
        for (int ii = 0; ii < 16; ++ii) {
            int j = tid + ii * TA;
            int row = j >> 2, part = j & 3;
            float4 v = *reinterpret_cast<const float4*>(
                x + (ll)(r0 + row) * 64 + c * 16 + part * 4);
            *reinterpret_cast<float4*>(&sh_x[swz(row, part)]) = v;
        }
        __syncthreads();

        #pragma unroll
        for (int p4 = 0; p4 < 4; ++p4) {
            float xv[4][4];
            #pragma unroll
            for (int r = 0; r < 4; ++r) {
                float4 v = *reinterpret_cast<const float4*>(&sh_x[swz(tid + r * TA, p4)]);
                xv[r][0] = v.x; xv[r][1] = v.y; xv[r][2] = v.z; xv[r][3] = v.w;
            }
            #pragma unroll
            for (int dd = 0; dd < 4; ++dd) {
                int k = c * 16 + p4 * 4 + dd;
                ull w[8];
                #pragma unroll
                for (int g = 0; g < 2; ++g) {
                    ulonglong2 a0 = shw2[(g * 64 + k) * 2];
                    ulonglong2 a1 = shw2[(g * 64 + k) * 2 + 1];
                    w[g * 4 + 0] = a0.x; w[g * 4 + 1] = a0.y;
                    w[g * 4 + 2] = a1.x; w[g * 4 + 3] = a1.y;
                }
                #pragma unroll
                for (int r = 0; r < 4; ++r) {
                    ull xx = pack2(xv[r][dd], xv[r][dd]);
                    #pragma unroll
                    for (int j = 0; j < 8; ++j) acc[r][j] = fma2(xx, w[j], acc[r][j]);
                }
            }
        }
    }

    // bias + tanh IN PLACE (acc = packed tanh pairs; feats P = (j>>2)*8 + (j&3)*2)
    #pragma unroll
    for (int r = 0; r < 4; ++r)
        #pragma unroll
        for (int j = 0; j < 8; ++j) {
            int P = (j >> 2) * 8 + (j & 3) * 2;
            float lo, hi; unpack2(acc[r][j], lo, hi);
            acc[r][j] = pack2(ftanh(lo + sb0[P]), ftanh(hi + sb0[P + 1]));
        }

    // partial stats over this block's 1024 rows -> scratch (deterministic)
    #pragma unroll
    for (int j = 0; j < 8; ++j) {
        float s0 = 0.f, q0 = 0.f, s1 = 0.f, q1 = 0.f;
        #pragma unroll
        for (int r = 0; r < 4; ++r) {
            float lo, hi; unpack2(acc[r][j], lo, hi);
            s0 += lo; q0 += lo * lo;
            s1 += hi; q1 += hi * hi;
        }
        #pragma unroll
        for (int o = 16; o; o >>= 1) {
            s0 += __shfl_xor_sync(0xffffffffu, s0, o);
            q0 += __shfl_xor_sync(0xffffffffu, q0, o);
            s1 += __shfl_xor_sync(0xffffffffu, s1, o);
            q1 += __shfl_xor_sync(0xffffffffu, q1, o);
        }
        if (lane == 0) {
            int P = (j >> 2) * 8 + (j & 3) * 2;
            red[P * NWA + warp]            = s0;
            red[(16 + P) * NWA + warp]     = q0;
            red[(P + 1) * NWA + warp]      = s1;
            red[(16 + P + 1) * NWA + warp] = q1;
        }
    }
    __syncthreads();
    if (tid < 16) {
        float s = 0.f, q = 0.f;
        #pragma unroll
        for (int w = 0; w < NWA; ++w) { s += red[tid * NWA + w]; q += red[(16 + tid) * NWA + w]; }
        g_ssum[rt][m0 * 8 + tid] = s;
        g_ssq[rt][m0 * 8 + tid]  = q;
    }

    // store RAW tanh via swizzled tile exchange (256-row chunks, coalesced 64B/row)
    float* tile = sh_x;
    #pragma unroll 1
    for (int q = 0; q < 4; ++q) {
        __syncthreads();
        // part p holds feats 4p..4p+3 = packed pairs j=2p, 2p+1
        #pragma unroll
        for (int p = 0; p < 4; ++p) {
            ulonglong2 v; v.x = acc[q][2 * p]; v.y = acc[q][2 * p + 1];
            *reinterpret_cast<ulonglong2*>(&tile[swz(tid, p)]) = v;
        }
        __syncthreads();
        #pragma unroll
        for (int ii = 0; ii < 4; ++ii) {
            int j = tid + ii * TA;
            int row = j >> 2, part = j & 3;
            int grow = r0 + q * 256 + row;
            *reinterpret_cast<float4*>(&out_t[(ll)grow * 65536 + m0 * 8 + part * 4]) =
                *reinterpret_cast<const float4*>(&tile[swz(row, part)]);
        }
    }
}

// ===================== Kernel B: fused normalize(t0) + aux0 + full L1 =====================
// Block = 1 root term, 512 threads, full batch (4 rows/thread).
#define TB 512
#define NWB 16

__global__ void __launch_bounds__(TB, 1)
l1_fused(const float* __restrict__ gp0,  const float* __restrict__ bep0,
         const float* __restrict__ Wa0p, const float* __restrict__ ba0p,
         const float* __restrict__ ga0p, const float* __restrict__ bea0p,
         const float* __restrict__ W1p,  const float* __restrict__ b1p,
         const float* __restrict__ g1p,  const float* __restrict__ be1p,
         const float* __restrict__ Wa1p, const float* __restrict__ ba1p,
         const float* __restrict__ ga1p, const float* __restrict__ bea1p,
         float* __restrict__ t0, float* __restrict__ t1,
         float* __restrict__ aux0, float* __restrict__ aux1)
{
    extern __shared__ float sm[];
    float* tile  = sm;               // [2048*16] swizzled chunk
    float* shw1  = sm + 2048 * 16;   // [512]
    float* cstA  = shw1 + 512;       // [64] child-feat BN scale
    float* cstB  = cstA + 64;        // [64]
    float* swa0  = cstB + 64;        // [128]
    float* sba0  = swa0 + 128;       // [16]
    float* sga0  = sba0 + 16;
    float* sbea0 = sga0 + 16;
    float* sb1   = sbea0 + 16;       // [8]
    float* sg1   = sb1 + 8;
    float* sbe1  = sg1 + 8;
    float* swa1  = sbe1 + 8;         // [16]
    float* sba1  = swa1 + 16;        // [2]
    float* sga1  = sba1 + 2;
    float* sbea1 = sga1 + 2;
    float* red   = sbea1 + 2;        // [16*NWB*2] = 512
    float* sA    = red + 512;        // [16] aux0 scale
    float* sB    = sA + 16;
    float* s1A   = sB + 16;          // [8]  t1 BN scale
    float* s1B   = s1A + 8;
    float* sa1A  = s1B + 8;          // [2]
    float* sa1B  = sa1A + 2;

    const int tid  = threadIdx.x;
    const int lane = tid & 31;
    const int warp = tid >> 5;
    const int m    = blockIdx.x;

    for (int i = tid; i < 512; i += TB) shw1[i] = W1p[(ll)m * 512 + i];
    if (tid < 64) {
        float s = g_ssum[0][m * 64 + tid] + g_ssum[1][m * 64 + tid];
        float q = g_ssq[0][m * 64 + tid]  + g_ssq[1][m * 64 + tid];
        float mu  = s * (1.f / 2048.f);
        float var = q * (1.f / 2048.f) - mu * mu;
        float a = gp0[m * 64 + tid] * rsqrtf(var + BN_EPS);
        cstA[tid] = a;
        cstB[tid] = bep0[m * 64 + tid] - mu * a;
    }
    if (tid < 128) swa0[tid] = Wa0p[m * 128 + tid];
    if (tid < 16) {
        sba0[tid]  = ba0p[m * 16 + tid];
        sga0[tid]  = ga0p[m * 16 + tid];
        sbea0[tid] = bea0p[m * 16 + tid];
    }
    if (tid < 8) { sb1[tid] = b1p[m * 8 + tid]; sg1[tid] = g1p[m * 8 + tid]; sbe1[tid] = be1p[m * 8 + tid]; }
    if (tid < 16) swa1[tid] = Wa1p[m * 16 + tid];
    if (tid < 2) { sba1[tid] = ba1p[m * 2 + tid]; sga1[tid] = ga1p[m * 2 + tid]; sbea1[tid] = bea1p[m * 2 + tid]; }

    ull acc[4][4];
    #pragma unroll
    for (int r = 0; r < 4; ++r)
        #pragma unroll
        for (int j = 0; j < 4; ++j) acc[r][j] = 0ull;
    float av[4][16];

    const ulonglong2* shw2 = reinterpret_cast<const ulonglong2*>(shw1);

    // ---- fused loop over 4 chunks of 16 child-feats (= 2 children each) ----
    #pragma unroll 1
    for (int c = 0; c < 4; ++c) {
        __syncthreads();   // params ready (c=0) / previous STG-out done
        #pragma unroll
        for (int ii = 0; ii < 16; ++ii) {
            int j = tid + ii * TB;
            int row = j >> 2, part = j & 3;
            float4 v = *reinterpret_cast<const float4*>(
                t0 + (ll)row * 65536 + m * 64 + c * 16 + part * 4);
            *reinterpret_cast<float4*>(&tile[swz(row, part)]) = v;
        }
        __syncthreads();

        #pragma unroll
        for (int r = 0; r < 4; ++r) {
            int row = tid + r * TB;
            float tn[16];
            #pragma unroll
            for (int p = 0; p < 4; ++p) {
                float4 v = *reinterpret_cast<const float4*>(&tile[swz(row, p)]);
                tn[p * 4 + 0] = fmaf(cstA[c * 16 + p * 4 + 0], v.x, cstB[c * 16 + p * 4 + 0]);
                tn[p * 4 + 1] = fmaf(cstA[c * 16 + p * 4 + 1], v.y, cstB[c * 16 + p * 4 + 1]);
                tn[p * 4 + 2] = fmaf(cstA[c * 16 + p * 4 + 2], v.z, cstB[c * 16 + p * 4 + 2]);
                tn[p * 4 + 3] = fmaf(cstA[c * 16 + p * 4 + 3], v.w, cstB[c * 16 + p * 4 + 3]);
            }
            // L1 GEMM partial (16 dims of 64)
            #pragma unroll
            for (int d = 0; d < 16; ++d) {
                int k = c * 16 + d;
                ulonglong2 w01 = shw2[k * 2];
                ulonglong2 w23 = shw2[k * 2 + 1];
                ull xx = pack2(tn[d], tn[d]);
                acc[r][0] = fma2(xx, w01.x, acc[r][0]);
                acc[r][1] = fma2(xx, w01.y, acc[r][1]);
                acc[r][2] = fma2(xx, w23.x, acc[r][2]);
                acc[r][3] = fma2(xx, w23.y, acc[r][3]);
            }
            // aux0 heads for children 2c, 2c+1
            #pragma unroll
            for (int l = 0; l < 2; ++l) {
                int g = c * 2 + l;
                #pragma unroll
                for (int k2 = 0; k2 < 2; ++k2) {
                    float a = sba0[g * 2 + k2];
                    #pragma unroll
                    for (int h = 0; h < 8; ++h)
                        a = fmaf(tn[l * 8 + h], swa0[(g * 8 + h) * 2 + k2], a);
                    av[r][c * 4 + l * 2 + k2] = ftanh(a);
                }
            }
            // normalized values back into tile (own rows only -> no race)
            #pragma unroll
            for (int p = 0; p < 4; ++p) {
                float4 o = make_float4(tn[p * 4], tn[p * 4 + 1], tn[p * 4 + 2], tn[p * 4 + 3]);
                *reinterpret_cast<float4*>(&tile[swz(row, p)]) = o;
            }
        }
        __syncthreads();
        // store normalized t0 chunk (coalesced)
        #pragma unroll
        for (int ii = 0; ii < 16; ++ii) {
            int j = tid + ii * TB;
            int row = j >> 2, part = j & 3;
            *reinterpret_cast<float4*>(t0 + (ll)row * 65536 + m * 64 + c * 16 + part * 4) =
                *reinterpret_cast<const float4*>(&tile[swz(row, part)]);
        }
    }

    // ---- aux0 batch stats (16 feats) + BN + coalesced store ----
    #pragma unroll
    for (int f = 0; f < 16; ++f) {
        float s = 0.f, q = 0.f;
        #pragma unroll
        for (int r = 0; r < 4; ++r) { float v = av[r][f]; s += v; q += v * v; }
        #pragma unroll
        for (int o = 16; o; o >>= 1) {
            s += __shfl_xor_sync(0xffffffffu, s, o);
            q += __shfl_xor_sync(0xffffffffu, q, o);
        }
        if (lane == 0) { red[f * NWB + warp] = s; red[(16 + f) * NWB + warp] = q; }
    }
    __syncthreads();
    if (tid < 16) {
        float s = 0.f, q = 0.f;
        #pragma unroll
        for (int w = 0; w < NWB; ++w) { s += red[tid * NWB + w]; q += red[(16 + tid) * NWB + w]; }
        float mu  = s * (1.f / 2048.f);
        float var = q * (1.f / 2048.f) - mu * mu;
        float a = sga0[tid] * rsqrtf(var + BN_EPS);
        sA[tid] = a;
        sB[tid] = sbea0[tid] - mu * a;
    }
    __syncthreads();

    #pragma unroll 1
    for (int q = 0; q < 4; ++q) {
        #pragma unroll
        for (int p = 0; p < 4; ++p) {
            float4 o;
            o.x = fmaf(sA[p * 4 + 0], av[q][p * 4 + 0], sB[p * 4 + 0]);
            o.y = fmaf(sA[p * 4 + 1], av[q][p * 4 + 1], sB[p * 4 + 1]);
            o.z = fmaf(sA[p * 4 + 2], av[q][p * 4 + 2], sB[p * 4 + 2]);
            o.w = fmaf(sA[p * 4 + 3], av[q][p * 4 + 3], sB[p * 4 + 3]);
            *reinterpret_cast<float4*>(&tile[swz(tid, p)]) = o;
        }
        __syncthreads();
        #pragma unroll
        for (int ii = 0; ii < 4; ++ii) {
            int j = tid + ii * TB;
            int row = j >> 2, part = j & 3;
            int grow = q * TB + row;
            *reinterpret_cast<float4*>(aux0 + (ll)grow * 16384 + m * 16 + part * 4) =
                *reinterpret_cast<const float4*>(&tile[swz(row, part)]);
        }
        __syncthreads();
    }

    // ---- L1: bias + tanh in place, BN, write t1, aux1 ----
    #pragma unroll
    for (int r = 0; r < 4; ++r)
        #pragma unroll
        for (int j = 0; j < 4; ++j) {
            float lo, hi; unpack2(acc[r][j], lo, hi);
            acc[r][j] = pack2(ftanh(lo + sb1[2 * j]), ftanh(hi + sb1[2 * j + 1]));
        }
    #pragma unroll
    for (int j = 0; j < 4; ++j) {
        float s0 = 0.f, q0 = 0.f, s1v = 0.f, q1v = 0.f;
        #pragma unroll
        for (int r = 0; r < 4; ++r) {
            float lo, hi; unpack2(acc[r][j], lo, hi);
            s0 += lo; q0 += lo * lo; s1v += hi; q1v += hi * hi;
        }
        #pragma unroll
        for (int o = 16; o; o >>= 1) {
            s0  += __shfl_xor_sync(0xffffffffu, s0, o);
            q0  += __shfl_xor_sync(0xffffffffu, q0, o);
            s1v += __shfl_xor_sync(0xffffffffu, s1v, o);
            q1v += __shfl_xor_sync(0xffffffffu, q1v, o);
        }
        if (lane == 0) {
            red[(2 * j) * NWB + warp]          = s0;
            red[(16 + 2 * j) * NWB + warp]     = q0;
            red[(2 * j + 1) * NWB + warp]      = s1v;
            red[(16 + 2 * j + 1) * NWB + warp] = q1v;
        }
    }
    __syncthreads();
    if (tid < 8) {
        float s = 0.f, q = 0.f;
        #pragma unroll
        for (int w = 0; w < NWB; ++w) { s += red[tid * NWB + w]; q += red[(16 + tid) * NWB + w]; }
        float mu  = s * (1.f / 2048.f);
        float var = q * (1.f / 2048.f) - mu * mu;
        float a = sg1[tid] * rsqrtf(var + BN_EPS);
        s1A[tid] = a;
        s1B[tid] = sbe1[tid] - mu * a;
    }
    __syncthreads();

    float av1[4][2];
    #pragma unroll
    for (int r = 0; r < 4; ++r) {
        int row = tid + r * TB;
        float tn[8];
        #pragma unroll
        for (int j = 0; j < 4; ++j) {
            float lo, hi; unpack2(acc[r][j], lo, hi);
            tn[2 * j]     = fmaf(s1A[2 * j],     lo, s1B[2 * j]);
            tn[2 * j + 1] = fmaf(s1A[2 * j + 1], hi, s1B[2 * j + 1]);
        }
        ll obase = (ll)row * 8192 + m * 8;
        *reinterpret_cast<float4*>(t1 + obase)     = make_float4(tn[0], tn[1], tn[2], tn[3]);
        *reinterpret_cast<float4*>(t1 + obase + 4) = make_float4(tn[4], tn[5], tn[6], tn[7]);
        #pragma unroll
        for (int k = 0; k < 2; ++k) {
            float a = sba1[k];
            #pragma unroll
            for (int h = 0; h < 8; ++h) a = fmaf(tn[h], swa1[h * 2 + k], a);
            av1[r][k] = ftanh(a);
        }
    }

    #pragma unroll
    for (int f = 0; f < 2; ++f) {
        float s = 0.f, q = 0.f;
        #pragma unroll
        for (int r = 0; r < 4; ++r) { float v = av1[r][f]; s += v; q += v * v; }
        #pragma unroll
        for (int o = 16; o; o >>= 1) {
            s += __shfl_xor_sync(0xffffffffu, s, o);
            q += __shfl_xor_sync(0xffffffffu, q, o);
        }
        if (lane == 0) { red[f * NWB + warp] = s; red[(16 + f) * NWB + warp] = q; }
    }
    __syncthreads();
    if (tid < 2) {
        float s = 0.f, q = 0.f;
        #pragma unroll
        for (int w = 0; w < NWB; ++w) { s += red[tid * NWB + w]; q += red[(16 + tid) * NWB + w]; }
        float mu  = s * (1.f / 2048.f);
        float var = q * (1.f / 2048.f) - mu * mu;
        float a = sga1[tid] * rsqrtf(var + BN_EPS);
        sa1A[tid] = a;
        sa1B[tid] = sbea1[tid] - mu * a;
    }
    __syncthreads();

    #pragma unroll
    for (int r = 0; r < 4; ++r) {
        int row = tid + r * TB;
        float2 v;
        v.x = fmaf(sa1A[0], av1[r][0], sa1B[0]);
        v.y = fmaf(sa1A[1], av1[r][1], sa1B[1]);
        *reinterpret_cast<float2*>(aux1 + (ll)row * 2048 + m * 2) = v;
    }
}

// Output layout: (aux0, aux1, t0, t1) flattened, fp32
static const ll OFF_A0 = 0;
static const ll OFF_A1 = 2048LL * 8192 * 2;            // 33,554,432
static const ll OFF_T0 = OFF_A1 + 2048LL * 1024 * 2;   // 37,748,736
static const ll OFF_T1 = OFF_T0 + 2048LL * 8192 * 8;   // 171,966,464

extern "C" void kernel_launch(void* const* d_in, const int* in_sizes, int n_in,
                              void* d_out, int out_size)
{
    const float* x    = (const float*)d_in[0];
    const float* W0   = (const float*)d_in[1];
    const float* b0   = (const float*)d_in[2];
    const float* g0   = (const float*)d_in[3];
    const float* be0  = (const float*)d_in[4];
    const float* Wa0  = (const float*)d_in[5];
    const float* ba0  = (const float*)d_in[6];
    const float* ga0  = (const float*)d_in[7];
    const float* bea0 = (const float*)d_in[8];
    const float* W1   = (const float*)d_in[9];
    const float* b1   = (const float*)d_in[10];
    const float* g1   = (const float*)d_in[11];
    const float* be1  = (const float*)d_in[12];
    const float* Wa1  = (const float*)d_in[13];
    const float* ba1  = (const float*)d_in[14];
    const float* ga1  = (const float*)d_in[15];
    const float* bea1 = (const float*)d_in[16];

    float* out  = (float*)d_out;
    float* aux0 = out + OFF_A0;
    float* aux1 = out + OFF_A1;
    float* t0   = out + OFF_T0;
    float* t1   = out + OFF_T1;

    const int sA = (1024 * 16 + 1024 + 16 + 16 * NWA * 2) * 4;             // ~69.3 KB
    const int sB = (2048 * 16 + 512 + 64 + 64 + 128 + 16 * 3 + 8 * 3 + 16
                    + 2 * 3 + 512 + 16 * 2 + 8 * 2 + 2 * 2) * 4;           // ~137 KB
    cudaFuncSetAttribute(reinterpret_cast<const void*>(l0_gemm),
                         cudaFuncAttributeMaxDynamicSharedMemorySize, sA);
    cudaFuncSetAttribute(reinterpret_cast<const void*>(l1_fused),
                         cudaFuncAttributeMaxDynamicSharedMemorySize, sB);

    // Kernel A: 4096 term-pairs x 2 row-halves; 2 blocks/SM resident
    l0_gemm<<<8192, TA, sA>>>(x, W0, b0, t0);

    // Kernel B: 1024 roots; finalize child BN + aux0 + full L1 path
    l1_fused<<<1024, TB, sB>>>(g0, be0, Wa0, ba0, ga0, bea0,
                               W1, b1, g1, be1, Wa1, ba1, ga1, bea1,
                               t0, t1, aux0, aux1);
}

// round 8
// speedup vs baseline: 1.7492x; 1.7492x over previous
#include <cuda_runtime.h>
#include <cstdint>

#define THREADS 512
#define NW (THREADS / 32)        // 16 warps
#define B_ROWS 2048
#define RPT (B_ROWS / THREADS)   // 4 rows per thread
#define BN_EPS 1e-5f

typedef unsigned long long ull;
typedef long long ll;

__device__ __forceinline__ ull pack2(float lo, float hi) {
    ull r; asm("mov.b64 %0, {%1, %2};" : "=l"(r) : "f"(lo), "f"(hi)); return r;
}
__device__ __forceinline__ void unpack2(ull v, float& lo, float& hi) {
    asm("mov.b64 {%0, %1}, %2;" : "=f"(lo), "=f"(hi) : "l"(v));
}
__device__ __forceinline__ ull fma2(ull a, ull b, ull c) {
    ull d; asm("fma.rn.f32x2 %0, %1, %2, %3;" : "=l"(d) : "l"(a), "l"(b), "l"(c)); return d;
}
// accurate tanh (~1e-7 rel): MUFU.TANH at ~5e-4 is too close to the 1e-3 gate
__device__ __forceinline__ float ftanh(float x) {
    float e = __expf(2.0f * x);
    return 1.0f - __fdividef(2.0f, e + 1.0f);
}
__device__ __forceinline__ uint32_t s2u(const void* p) {
    return (uint32_t)__cvta_generic_to_shared(p);
}

// XOR-swizzled float4-column index for a [rows][16]-float smem tile (store tile)
__device__ __forceinline__ int swz16(int row, int part) {
    return row * 16 + (((part + (row >> 1)) & 3) << 2);
}
// XOR-swizzled float4-column index for a [rows][8]-float smem tile (x staging)
// Conflict-free for cp.async writes (2 lanes/row) and row-per-lane LDS.128 reads.
__device__ __forceinline__ int swz8(int row, int part) {
    return row * 8 + (((part + (row >> 1) + (row >> 2)) & 1) << 2);
}

// ============================ L0 kernel ============================
// Block = 2 consecutive terms over the full batch (4 rows/thread in registers).
// x staged via double-buffered cp.async (8-dim chunks, 32B per row, L2-resident),
// overlapping chunk c+1's loads with chunk c's FMA work. BN + aux head fused.
__global__ void __launch_bounds__(THREADS, 1)
l0_kernel(const float* __restrict__ xin,
          const float* __restrict__ Wp,  const float* __restrict__ bp,
          const float* __restrict__ gp,  const float* __restrict__ bep,
          const float* __restrict__ Wap, const float* __restrict__ bap,
          const float* __restrict__ gap, const float* __restrict__ beap,
          float* __restrict__ out_t, float* __restrict__ out_a, int M)
{
    constexpr int G  = 2;
    constexpr int F  = 16;
    constexpr int FA = 4;
    constexpr int XB = B_ROWS * 8;           // floats per staging buffer

    extern __shared__ float sm[];
    float* bx0    = sm;                      // [2048*8] staging buf 0; reused as store tile
    float* bx1    = sm + XB;                 // [2048*8] staging buf 1
    float* sh_w   = bx1 + XB;                // [1024]
    float* red    = sh_w + 1024;             // [F*NW*2]
    float* stA    = red + F * NW * 2;        // [16]
    float* stB    = stA + F;
    float* saA    = stB + F;                 // [4]
    float* saB    = saA + FA;
    float* sb0    = saB + FA;                // [16]
    float* sg0    = sb0 + F;
    float* sbe0   = sg0 + F;
    float* swa    = sbe0 + F;                // [32]
    float* sba    = swa + G * 16;            // [4]
    float* sga    = sba + FA;
    float* sbea   = sga + FA;

    const int tid  = threadIdx.x;
    const int lane = tid & 31;
    const int warp = tid >> 5;
    const int m0   = blockIdx.x * G;

    // ---- params to smem ----
    for (int i = tid; i < 1024; i += THREADS) sh_w[i] = Wp[(ll)m0 * 512 + i];
    if (tid < F) {
        sb0[tid]  = bp[m0 * 8 + tid];
        sg0[tid]  = gp[m0 * 8 + tid];
        sbe0[tid] = bep[m0 * 8 + tid];
    }
    if (tid < G * 16) swa[tid] = Wap[m0 * 16 + tid];
    if (tid < FA) {
        sba[tid]  = bap[m0 * 2 + tid];
        sga[tid]  = gap[m0 * 2 + tid];
        sbea[tid] = beap[m0 * 2 + tid];
    }

    const uint32_t bu[2] = { s2u(bx0), s2u(bx1) };

    // ---- Phase 1: GEMM (64 -> 16), 8 chunks of 8 dims, double-buffered cp.async ----
    ull acc[RPT][8];
    #pragma unroll
    for (int r = 0; r < RPT; ++r)
        #pragma unroll
        for (int j = 0; j < 8; ++j) acc[r][j] = 0ull;

    const ulonglong2* shw2 = reinterpret_cast<const ulonglong2*>(sh_w);

    // stage chunk 0
    #pragma unroll
    for (int ii = 0; ii < 8; ++ii) {
        int j = tid + ii * THREADS;
        int row = j >> 1, part = j & 1;
        const float* g = xin + (ll)row * 64 + part * 4;
        uint32_t s = bu[0] + swz8(row, part) * 4;
        asm volatile("cp.async.cg.shared.global [%0], [%1], 16;" :: "r"(s), "l"(g));
    }
    asm volatile("cp.async.commit_group;" ::: "memory");

    #pragma unroll 1
    for (int c = 0; c < 8; ++c) {
        if (c < 7) {
            uint32_t b = bu[(c + 1) & 1];
            #pragma unroll
            for (int ii = 0; ii < 8; ++ii) {
                int j = tid + ii * THREADS;
                int row = j >> 1, part = j & 1;
                const float* g = xin + (ll)row * 64 + (c + 1) * 8 + part * 4;
                uint32_t s = b + swz8(row, part) * 4;
                asm volatile("cp.async.cg.shared.global [%0], [%1], 16;" :: "r"(s), "l"(g));
            }
            asm volatile("cp.async.commit_group;" ::: "memory");
            asm volatile("cp.async.wait_group 1;" ::: "memory");
        } else {
            asm volatile("cp.async.wait_group 0;" ::: "memory");
        }
        __syncthreads();   // chunk c visible to all (also orders param writes at c=0)

        const float* buf = (c & 1) ? bx1 : bx0;
        #pragma unroll
        for (int p4 = 0; p4 < 2; ++p4) {
            float xv[RPT][4];
            #pragma unroll
            for (int r = 0; r < RPT; ++r) {
                const float4 v = *reinterpret_cast<const float4*>(
                    &buf[swz8(tid + r * THREADS, p4)]);
                xv[r][0] = v.x; xv[r][1] = v.y; xv[r][2] = v.z; xv[r][3] = v.w;
            }
            #pragma unroll
            for (int dd = 0; dd < 4; ++dd) {
                int k = c * 8 + p4 * 4 + dd;
                ull w[8];
                #pragma unroll
                for (int g = 0; g < 2; ++g) {
                    ulonglong2 w01 = shw2[(g * 64 + k) * 2];
                    ulonglong2 w23 = shw2[(g * 64 + k) * 2 + 1];
                    w[g * 4 + 0] = w01.x; w[g * 4 + 1] = w01.y;
                    w[g * 4 + 2] = w23.x; w[g * 4 + 3] = w23.y;
                }
                #pragma unroll
                for (int r = 0; r < RPT; ++r) {
                    ull xx = pack2(xv[r][dd], xv[r][dd]);
                    #pragma unroll
                    for (int j = 0; j < 8; ++j) acc[r][j] = fma2(xx, w[j], acc[r][j]);
                }
            }
        }
        __syncthreads();   // buf consumed before next overwrite
    }

    // ---- Phase 2: bias + tanh (separate tv registers; best measured variant) ----
    float tv[RPT][F];
    #pragma unroll
    for (int r = 0; r < RPT; ++r)
        #pragma unroll
        for (int g = 0; g < 2; ++g)
            #pragma unroll
            for (int p = 0; p < 4; ++p) {
                float lo, hi; unpack2(acc[r][g * 4 + p], lo, hi);
                int P = g * 8 + 2 * p;
                tv[r][P]     = ftanh(lo + sb0[P]);
                tv[r][P + 1] = ftanh(hi + sb0[P + 1]);
            }

    // ---- batch stats ----
    #pragma unroll
    for (int f = 0; f < F; ++f) {
        float s = 0.f, ss = 0.f;
        #pragma unroll
        for (int r = 0; r < RPT; ++r) { float v = tv[r][f]; s += v; ss += v * v; }
        #pragma unroll
        for (int o = 16; o; o >>= 1) {
            s  += __shfl_xor_sync(0xffffffffu, s, o);
            ss += __shfl_xor_sync(0xffffffffu, ss, o);
        }
        if (lane == 0) { red[f * NW + warp] = s; red[(F + f) * NW + warp] = ss; }
    }
    __syncthreads();
    if (tid < F) {
        int f = tid;
        float s = 0.f, ss = 0.f;
        #pragma unroll
        for (int w = 0; w < NW; ++w) { s += red[f * NW + w]; ss += red[(F + f) * NW + w]; }
        float mu  = s  * (1.f / B_ROWS);
        float var = ss * (1.f / B_ROWS) - mu * mu;
        float a   = sg0[f] * rsqrtf(var + BN_EPS);
        stA[f] = a;
        stB[f] = sbe0[f] - mu * a;
    }
    __syncthreads();

    // ---- Phase 3: normalize -> swizzled tile -> coalesced STG; aux in same pass ----
    float* tile = bx0;
    float av[RPT][FA];
    #pragma unroll 1
    for (int q = 0; q < RPT; ++q) {
        float tn[F];
        #pragma unroll
        for (int f = 0; f < F; ++f) tn[f] = fmaf(stA[f], tv[q][f], stB[f]);

        #pragma unroll
        for (int part = 0; part < 4; ++part) {
            float4 v = make_float4(tn[part * 4], tn[part * 4 + 1],
                                   tn[part * 4 + 2], tn[part * 4 + 3]);
            *reinterpret_cast<float4*>(&tile[swz16(tid, part)]) = v;
        }
        #pragma unroll
        for (int g = 0; g < 2; ++g)
            #pragma unroll
            for (int k = 0; k < 2; ++k) {
                float a = sba[g * 2 + k];
                #pragma unroll
                for (int h = 0; h < 8; ++h)
                    a = fmaf(tn[g * 8 + h], swa[(g * 8 + h) * 2 + k], a);
                av[q][g * 2 + k] = ftanh(a);
            }
        __syncthreads();

        #pragma unroll
        for (int jj = 0; jj < 4; ++jj) {
            int j    = tid + jj * THREADS;
            int row  = j >> 2;
            int part = j & 3;
            int grow = q * THREADS + row;
            *reinterpret_cast<float4*>(&out_t[(ll)grow * M * 8 + m0 * 8 + part * 4]) =
                *reinterpret_cast<const float4*>(&tile[swz16(row, part)]);
        }
        __syncthreads();
    }

    // ---- Phase 4: aux stats + store ----
    #pragma unroll
    for (int f = 0; f < FA; ++f) {
        float s = 0.f, ss = 0.f;
        #pragma unroll
        for (int r = 0; r < RPT; ++r) { float v = av[r][f]; s += v; ss += v * v; }
        #pragma unroll
        for (int o = 16; o; o >>= 1) {
            s  += __shfl_xor_sync(0xffffffffu, s, o);
            ss += __shfl_xor_sync(0xffffffffu, ss, o);
        }
        if (lane == 0) { red[f * NW + warp] = s; red[(FA + f) * NW + warp] = ss; }
    }
    __syncthreads();
    if (tid < FA) {
        int f = tid;
        float s = 0.f, ss = 0.f;
        #pragma unroll
        for (int w = 0; w < NW; ++w) { s += red[f * NW + w]; ss += red[(FA + f) * NW + w]; }
        float mu  = s  * (1.f / B_ROWS);
        float var = ss * (1.f / B_ROWS) - mu * mu;
        float a   = sga[f] * rsqrtf(var + BN_EPS);
        saA[f] = a;
        saB[f] = sbea[f] - mu * a;
    }
    __syncthreads();

    #pragma unroll
    for (int r = 0; r < RPT; ++r) {
        int b = tid + r * THREADS;
        ll obase = ((ll)b * M + m0) * 2;
        float4 v;
        v.x = fmaf(saA[0], av[r][0], saB[0]);
        v.y = fmaf(saA[1], av[r][1], saB[1]);
        v.z = fmaf(saA[2], av[r][2], saB[2]);
        v.w = fmaf(saA[3], av[r][3], saB[3]);
        *reinterpret_cast<float4*>(&out_a[obase]) = v;
    }
}

// ============================ L1 kernel ============================
// Block = 1 root term; t0 slice read directly (DRAM) with next-chunk register
// prefetch to double per-thread MLP; full batch in registers.
__global__ void __launch_bounds__(THREADS, 1)
l1_kernel(const float* __restrict__ xin,
          const float* __restrict__ Wp,  const float* __restrict__ bp,
          const float* __restrict__ gp,  const float* __restrict__ bep,
          const float* __restrict__ Wap, const float* __restrict__ bap,
          const float* __restrict__ gap, const float* __restrict__ beap,
          float* __restrict__ out_t, float* __restrict__ out_a, int M)
{
    constexpr int F = 8, FA = 2;

    __shared__ float sh_w[512];
    __shared__ float sb0[F], sg0[F], sbe0[F];
    __shared__ float swa[16];
    __shared__ float sba[FA], sga[FA], sbea[FA];
    __shared__ float red[F * NW * 2];
    __shared__ float stA[F], stB[F];
    __shared__ float saA[FA], saB[FA];

    const int tid  = threadIdx.x;
    const int lane = tid & 31;
    const int warp = tid >> 5;
    const int m0   = blockIdx.x;

    for (int i = tid; i < 512; i += THREADS) sh_w[i] = Wp[(ll)m0 * 512 + i];
    if (tid < F) {
        sb0[tid]  = bp[m0 * 8 + tid];
        sg0[tid]  = gp[m0 * 8 + tid];
        sbe0[tid] = bep[m0 * 8 + tid];
    }
    if (tid < 16) swa[tid] = Wap[m0 * 16 + tid];
    if (tid < FA) {
        sba[tid]  = bap[m0 * 2 + tid];
        sga[tid]  = gap[m0 * 2 + tid];
        sbea[tid] = beap[m0 * 2 + tid];
    }
    __syncthreads();

    const float* xptr[RPT];
    #pragma unroll
    for (int r = 0; r < RPT; ++r)
        xptr[r] = xin + (ll)(tid + r * THREADS) * 65536 + (ll)m0 * 64;

    ull acc[RPT][4];
    #pragma unroll
    for (int r = 0; r < RPT; ++r)
        #pragma unroll
        for (int j = 0; j < 4; ++j) acc[r][j] = 0ull;

    // prefetch chunk 0
    float4 nxt[RPT];
    #pragma unroll
    for (int r = 0; r < RPT; ++r)
        nxt[r] = *reinterpret_cast<const float4*>(xptr[r]);

    #pragma unroll 1
    for (int c = 0; c < 16; ++c) {
        float4 cur[RPT];
        #pragma unroll
        for (int r = 0; r < RPT; ++r) cur[r] = nxt[r];
        if (c < 15) {
            #pragma unroll
            for (int r = 0; r < RPT; ++r)
                nxt[r] = *reinterpret_cast<const float4*>(xptr[r] + (c + 1) * 4);
        }
        float xv[RPT][4];
        #pragma unroll
        for (int r = 0; r < RPT; ++r) {
            xv[r][0] = cur[r].x; xv[r][1] = cur[r].y;
            xv[r][2] = cur[r].z; xv[r][3] = cur[r].w;
        }
        #pragma unroll
        for (int dd = 0; dd < 4; ++dd) {
            ull w[4];
            #pragma unroll
            for (int p = 0; p < 4; ++p)
                w[p] = *reinterpret_cast<const ull*>(&sh_w[(c * 4 + dd) * 8 + 2 * p]);
            #pragma unroll
            for (int r = 0; r < RPT; ++r) {
                ull xx = pack2(xv[r][dd], xv[r][dd]);
                #pragma unroll
                for (int j = 0; j < 4; ++j) acc[r][j] = fma2(xx, w[j], acc[r][j]);
            }
        }
    }

    float tv[RPT][F];
    #pragma unroll
    for (int r = 0; r < RPT; ++r)
        #pragma unroll
        for (int p = 0; p < 4; ++p) {
            float lo, hi; unpack2(acc[r][p], lo, hi);
            int P = 2 * p;
            tv[r][P]     = ftanh(lo + sb0[P]);
            tv[r][P + 1] = ftanh(hi + sb0[P + 1]);
        }

    #pragma unroll
    for (int f = 0; f < F; ++f) {
        float s = 0.f, ss = 0.f;
        #pragma unroll
        for (int r = 0; r < RPT; ++r) { float v = tv[r][f]; s += v; ss += v * v; }
        #pragma unroll
        for (int o = 16; o; o >>= 1) {
            s  += __shfl_xor_sync(0xffffffffu, s, o);
            ss += __shfl_xor_sync(0xffffffffu, ss, o);
        }
        if (lane == 0) { red[f * NW + warp] = s; red[(F + f) * NW + warp] = ss; }
    }
    __syncthreads();
    if (tid < F) {
        int f = tid;
        float s = 0.f, ss = 0.f;
        #pragma unroll
        for (int w = 0; w < NW; ++w) { s += red[f * NW + w]; ss += red[(F + f) * NW + w]; }
        float mu  = s  * (1.f / B_ROWS);
        float var = ss * (1.f / B_ROWS) - mu * mu;
        float a   = sg0[f] * rsqrtf(var + BN_EPS);
        stA[f] = a;
        stB[f] = sbe0[f] - mu * a;
    }
    __syncthreads();

    float av[RPT][FA];
    #pragma unroll
    for (int r = 0; r < RPT; ++r) {
        int b = tid + r * THREADS;
        float tn[F];
        #pragma unroll
        for (int f = 0; f < F; ++f) tn[f] = fmaf(stA[f], tv[r][f], stB[f]);

        ll obase = ((ll)b * M + m0) * 8;
        #pragma unroll
        for (int q = 0; q < 2; ++q) {
            float4 v = make_float4(tn[q * 4], tn[q * 4 + 1], tn[q * 4 + 2], tn[q * 4 + 3]);
            *reinterpret_cast<float4*>(&out_t[obase + q * 4]) = v;
        }
        #pragma unroll
        for (int k = 0; k < 2; ++k) {
            float a = sba[k];
            #pragma unroll
            for (int h = 0; h < 8; ++h)
                a = fmaf(tn[h], swa[h * 2 + k], a);
            av[r][k] = ftanh(a);
        }
    }

    #pragma unroll
    for (int f = 0; f < FA; ++f) {
        float s = 0.f, ss = 0.f;
        #pragma unroll
        for (int r = 0; r < RPT; ++r) { float v = av[r][f]; s += v; ss += v * v; }
        #pragma unroll
        for (int o = 16; o; o >>= 1) {
            s  += __shfl_xor_sync(0xffffffffu, s, o);
            ss += __shfl_xor_sync(0xffffffffu, ss, o);
        }
        if (lane == 0) { red[f * NW + warp] = s; red[(FA + f) * NW + warp] = ss; }
    }
    __syncthreads();
    if (tid < FA) {
        int f = tid;
        float s = 0.f, ss = 0.f;
        #pragma unroll
        for (int w = 0; w < NW; ++w) { s += red[f * NW + w]; ss += red[(FA + f) * NW + w]; }
        float mu  = s  * (1.f / B_ROWS);
        float var = ss * (1.f / B_ROWS) - mu * mu;
        float a   = sga[f] * rsqrtf(var + BN_EPS);
        saA[f] = a;
        saB[f] = sbea[f] - mu * a;
    }
    __syncthreads();

    #pragma unroll
    for (int r = 0; r < RPT; ++r) {
        int b = tid + r * THREADS;
        ll obase = ((ll)b * M + m0) * 2;
        float2 v;
        v.x = fmaf(saA[0], av[r][0], saB[0]);
        v.y = fmaf(saA[1], av[r][1], saB[1]);
        *reinterpret_cast<float2*>(&out_a[obase]) = v;
    }
}

// Output layout: (aux0, aux1, t0, t1) flattened, fp32
static const ll OFF_A0 = 0;
static const ll OFF_A1 = 2048LL * 8192 * 2;            // 33,554,432
static const ll OFF_T0 = OFF_A1 + 2048LL * 1024 * 2;   // 37,748,736
static const ll OFF_T1 = OFF_T0 + 2048LL * 8192 * 8;   // 171,966,464

extern "C" void kernel_launch(void* const* d_in, const int* in_sizes, int n_in,
                              void* d_out, int out_size)
{
    const float* x    = (const float*)d_in[0];
    const float* W0   = (const float*)d_in[1];
    const float* b0   = (const float*)d_in[2];
    const float* g0   = (const float*)d_in[3];
    const float* be0  = (const float*)d_in[4];
    const float* Wa0  = (const float*)d_in[5];
    const float* ba0  = (const float*)d_in[6];
    const float* ga0  = (const float*)d_in[7];
    const float* bea0 = (const float*)d_in[8];
    const float* W1   = (const float*)d_in[9];
    const float* b1   = (const float*)d_in[10];
    const float* g1   = (const float*)d_in[11];
    const float* be1  = (const float*)d_in[12];
    const float* Wa1  = (const float*)d_in[13];
    const float* ba1  = (const float*)d_in[14];
    const float* ga1  = (const float*)d_in[15];
    const float* bea1 = (const float*)d_in[16];

    float* out  = (float*)d_out;
    float* aux0 = out + OFF_A0;
    float* aux1 = out + OFF_A1;
    float* t0   = out + OFF_T0;
    float* t1   = out + OFF_T1;

    // L0 dynamic smem: 2 staging buffers (2048*8 each) + weights/params/reduction
    const int s0 = (2 * B_ROWS * 8 + 1024 + 16 * NW * 2 + 2 * 16 + 2 * 4
                    + 3 * 16 + 32 + 3 * 4) * 4;   // ~138 KB
    cudaFuncSetAttribute(reinterpret_cast<const void*>(l0_kernel),
                         cudaFuncAttributeMaxDynamicSharedMemorySize, s0);

    // Layer 0: 8192 terms, 2 per block; x L2-resident, streamed via cp.async
    l0_kernel<<<8192 / 2, THREADS, s0>>>(
        x, W0, b0, g0, be0, Wa0, ba0, ga0, bea0, t0, aux0, 8192);

    // Layer 1: 1024 roots; direct loads + register prefetch
    l1_kernel<<<1024, THREADS>>>(
        t0, W1, b1, g1, be1, Wa1, ba1, ga1, bea1, t1, aux1, 1024);
}

// round 10
// speedup vs baseline: 1.8763x; 1.0727x over previous
#include <cuda_runtime.h>

#define THREADS 512
#define NW (THREADS / 32)        // 16 warps
#define B_ROWS 2048
#define RPT (B_ROWS / THREADS)   // 4 rows per thread
#define BN_EPS 1e-5f

typedef unsigned long long ull;
typedef long long ll;

__device__ __forceinline__ ull pack2(float lo, float hi) {
    ull r; asm("mov.b64 %0, {%1, %2};" : "=l"(r) : "f"(lo), "f"(hi)); return r;
}
__device__ __forceinline__ void unpack2(ull v, float& lo, float& hi) {
    asm("mov.b64 {%0, %1}, %2;" : "=f"(lo), "=f"(hi) : "l"(v));
}
__device__ __forceinline__ ull fma2(ull a, ull b, ull c) {
    ull d; asm("fma.rn.f32x2 %0, %1, %2, %3;" : "=l"(d) : "l"(a), "l"(b), "l"(c)); return d;
}
// accurate tanh (~1e-7 rel): MUFU.TANH at ~5e-4 is too close to the 1e-3 gate
__device__ __forceinline__ float ftanh(float x) {
    float e = __expf(2.0f * x);
    return 1.0f - __fdividef(2.0f, e + 1.0f);
}

// ============================ L0 kernel ============================
// Block = 2 consecutive terms over the full batch (4 rows/thread in registers).
// x staged TRANSPOSED in smem: xT[d][row] with octet-rotation permutation
//   idx(d,row) = d*2048 + (row & ~31) + ((row + 8*(d>>2)) & 31)
// -> conflict-free STS.32 staging writes AND conflict-free LDS.32 readback
// (row-major [row][16] layouts have unavoidable 4-way readback conflicts:
//  32 lanes reading 16B from 32 rows of 64B stride hit each bank 4x).
// The t-store tile uses the same transposed trick.
__global__ void __launch_bounds__(THREADS, 1)
l0_kernel(const float* __restrict__ xin,
          const float* __restrict__ Wp,  const float* __restrict__ bp,
          const float* __restrict__ gp,  const float* __restrict__ bep,
          const float* __restrict__ Wap, const float* __restrict__ bap,
          const float* __restrict__ gap, const float* __restrict__ beap,
          float* __restrict__ out_t, float* __restrict__ out_a, int M)
{
    constexpr int G  = 2;
    constexpr int F  = 16;
    constexpr int FA = 4;

    extern __shared__ float sm[];
    float* xT     = sm;                      // [16][2048] permuted; reused as store tile
    float* sh_w   = sm + 16 * B_ROWS;        // [1024]
    float* red    = sh_w + 1024;             // [F*NW*2]
    float* stA    = red + F * NW * 2;        // [16]
    float* stB    = stA + F;
    float* saA    = stB + F;                 // [4]
    float* saB    = saA + FA;
    float* sb0    = saB + FA;                // [16]
    float* sg0    = sb0 + F;
    float* sbe0   = sg0 + F;
    float* swa    = sbe0 + F;                // [32]
    float* sba    = swa + G * 16;            // [4]
    float* sga    = sba + FA;
    float* sbea   = sga + FA;

    const int tid  = threadIdx.x;
    const int lane = tid & 31;
    const int warp = tid >> 5;
    const int m0   = blockIdx.x * G;

    // ---- params to smem ----
    for (int i = tid; i < 1024; i += THREADS) sh_w[i] = Wp[(ll)m0 * 512 + i];
    if (tid < F) {
        sb0[tid]  = bp[m0 * 8 + tid];
        sg0[tid]  = gp[m0 * 8 + tid];
        sbe0[tid] = bep[m0 * 8 + tid];
    }
    if (tid < G * 16) swa[tid] = Wap[m0 * 16 + tid];
    if (tid < FA) {
        sba[tid]  = bap[m0 * 2 + tid];
        sga[tid]  = gap[m0 * 2 + tid];
        sbea[tid] = beap[m0 * 2 + tid];
    }

    // per-row permuted addresses for readback: a[r][q] for q = d>>2
    int ra[RPT][4];
    #pragma unroll
    for (int r = 0; r < RPT; ++r) {
        int row = tid + r * THREADS;
        int b32 = row & ~31;
        #pragma unroll
        for (int q = 0; q < 4; ++q) ra[r][q] = b32 + ((row + 8 * q) & 31);
    }

    // ---- Phase 1: GEMM (64 -> 16), 4 chunks of 16 dims ----
    ull acc[RPT][8];
    #pragma unroll
    for (int r = 0; r < RPT; ++r)
        #pragma unroll
        for (int j = 0; j < 8; ++j) acc[r][j] = 0ull;

    const ulonglong2* shw2 = reinterpret_cast<const ulonglong2*>(sh_w);

    #pragma unroll 1
    for (int c = 0; c < 4; ++c) {
        __syncthreads();   // previous chunk consumed (also orders param writes at c=0)
        // stage chunk c transposed: 2048 rows x 4 parts = 8192 items (16 iters)
        #pragma unroll
        for (int ii = 0; ii < 16; ++ii) {
            int j   = tid + ii * THREADS;
            int row = j >> 2;
            int p   = j & 3;
            const float4 v = *reinterpret_cast<const float4*>(
                xin + (ll)row * 64 + c * 16 + p * 4);
            int base = (row & ~31) + ((row + 8 * p) & 31);
            xT[(p * 4 + 0) * B_ROWS + base] = v.x;
            xT[(p * 4 + 1) * B_ROWS + base] = v.y;
            xT[(p * 4 + 2) * B_ROWS + base] = v.z;
            xT[(p * 4 + 3) * B_ROWS + base] = v.w;
        }
        __syncthreads();

        #pragma unroll
        for (int d = 0; d < 16; ++d) {
            int q = d >> 2;
            float xv[RPT];
            #pragma unroll
            for (int r = 0; r < RPT; ++r) xv[r] = xT[d * B_ROWS + ra[r][q]];

            int k = c * 16 + d;
            ull w[8];
            #pragma unroll
            for (int g = 0; g < 2; ++g) {
                ulonglong2 w01 = shw2[(g * 64 + k) * 2];
                ulonglong2 w23 = shw2[(g * 64 + k) * 2 + 1];
                w[g * 4 + 0] = w01.x; w[g * 4 + 1] = w01.y;
                w[g * 4 + 2] = w23.x; w[g * 4 + 3] = w23.y;
            }
            #pragma unroll
            for (int r = 0; r < RPT; ++r) {
                ull xx = pack2(xv[r], xv[r]);
                #pragma unroll
                for (int j = 0; j < 8; ++j) acc[r][j] = fma2(xx, w[j], acc[r][j]);
            }
        }
    }

    // ---- Phase 2: bias + tanh (separate tv registers) ----
    float tv[RPT][F];
    #pragma unroll
    for (int r = 0; r < RPT; ++r)
        #pragma unroll
        for (int g = 0; g < 2; ++g)
            #pragma unroll
            for (int p = 0; p < 4; ++p) {
                float lo, hi; unpack2(acc[r][g * 4 + p], lo, hi);
                int P = g * 8 + 2 * p;
                tv[r][P]     = ftanh(lo + sb0[P]);
                tv[r][P + 1] = ftanh(hi + sb0[P + 1]);
            }

    // ---- batch stats ----
    #pragma unroll
    for (int f = 0; f < F; ++f) {
        float s = 0.f, ss = 0.f;
        #pragma unroll
        for (int r = 0; r < RPT; ++r) { float v = tv[r][f]; s += v; ss += v * v; }
        #pragma unroll
        for (int o = 16; o; o >>= 1) {
            s  += __shfl_xor_sync(0xffffffffu, s, o);
            ss += __shfl_xor_sync(0xffffffffu, ss, o);
        }
        if (lane == 0) { red[f * NW + warp] = s; red[(F + f) * NW + warp] = ss; }
    }
    __syncthreads();
    if (tid < F) {
        int f = tid;
        float s = 0.f, ss = 0.f;
        #pragma unroll
        for (int w = 0; w < NW; ++w) { s += red[f * NW + w]; ss += red[(F + f) * NW + w]; }
        float mu  = s  * (1.f / B_ROWS);
        float var = ss * (1.f / B_ROWS) - mu * mu;
        float a   = sg0[f] * rsqrtf(var + BN_EPS);
        stA[f] = a;
        stB[f] = sbe0[f] - mu * a;
    }
    __syncthreads();

    // ---- Phase 3: normalize -> transposed tile -> coalesced STG; aux in same pass ----
    // tile layout: [16 feats][512 rows] with the same octet rotation:
    //   tidx(f,row) = f*512 + (row & ~31) + ((row + 8*(f>>2)) & 31)
    float* tile = xT;   // reuse (GEMM done)
    float av[RPT][FA];
    const int tb32 = tid & ~31;
    #pragma unroll 1
    for (int q = 0; q < RPT; ++q) {
        float tn[F];
        #pragma unroll
        for (int f = 0; f < F; ++f) tn[f] = fmaf(stA[f], tv[q][f], stB[f]);

        #pragma unroll
        for (int f = 0; f < F; ++f)
            tile[f * 512 + tb32 + ((tid + 8 * (f >> 2)) & 31)] = tn[f];

        #pragma unroll
        for (int g = 0; g < 2; ++g)
            #pragma unroll
            for (int k = 0; k < 2; ++k) {
                float a = sba[g * 2 + k];
                #pragma unroll
                for (int h = 0; h < 8; ++h)
                    a = fmaf(tn[g * 8 + h], swa[(g * 8 + h) * 2 + k], a);
                av[q][g * 2 + k] = ftanh(a);
            }
        __syncthreads();

        // 512 rows x 4 parts = 2048 items (4 iters)
        #pragma unroll
        for (int ii = 0; ii < 4; ++ii) {
            int j   = tid + ii * THREADS;
            int row = j >> 2;
            int p   = j & 3;
            int rb  = (row & ~31) + ((row + 8 * p) & 31);
            float4 v;
            v.x = tile[(p * 4 + 0) * 512 + rb];
            v.y = tile[(p * 4 + 1) * 512 + rb];
            v.z = tile[(p * 4 + 2) * 512 + rb];
            v.w = tile[(p * 4 + 3) * 512 + rb];
            int grow = q * THREADS + row;
            *reinterpret_cast<float4*>(&out_t[(ll)grow * M * 8 + m0 * 8 + p * 4]) = v;
        }
        __syncthreads();
    }

    // ---- Phase 4: aux stats + store ----
    #pragma unroll
    for (int f = 0; f < FA; ++f) {
        float s = 0.f, ss = 0.f;
        #pragma unroll
        for (int r = 0; r < RPT; ++r) { float v = av[r][f]; s += v; ss += v * v; }
        #pragma unroll
        for (int o = 16; o; o >>= 1) {
            s  += __shfl_xor_sync(0xffffffffu, s, o);
            ss += __shfl_xor_sync(0xffffffffu, ss, o);
        }
        if (lane == 0) { red[f * NW + warp] = s; red[(FA + f) * NW + warp] = ss; }
    }
    __syncthreads();
    if (tid < FA) {
        int f = tid;
        float s = 0.f, ss = 0.f;
        #pragma unroll
        for (int w = 0; w < NW; ++w) { s += red[f * NW + w]; ss += red[(FA + f) * NW + w]; }
        float mu  = s  * (1.f / B_ROWS);
        float var = ss * (1.f / B_ROWS) - mu * mu;
        float a   = sga[f] * rsqrtf(var + BN_EPS);
        saA[f] = a;
        saB[f] = sbea[f] - mu * a;
    }
    __syncthreads();

    #pragma unroll
    for (int r = 0; r < RPT; ++r) {
        int b = tid + r * THREADS;
        ll obase = ((ll)b * M + m0) * 2;
        float4 v;
        v.x = fmaf(saA[0], av[r][0], saB[0]);
        v.y = fmaf(saA[1], av[r][1], saB[1]);
        v.z = fmaf(saA[2], av[r][2], saB[2]);
        v.w = fmaf(saA[3], av[r][3], saB[3]);
        *reinterpret_cast<float4*>(&out_a[obase]) = v;
    }
}

// ============================ L1 kernel (R6 verbatim — best measured 215us) ============================
__global__ void __launch_bounds__(THREADS, 1)
l1_kernel(const float* __restrict__ xin,
          const float* __restrict__ Wp,  const float* __restrict__ bp,
          const float* __restrict__ gp,  const float* __restrict__ bep,
          const float* __restrict__ Wap, const float* __restrict__ bap,
          const float* __restrict__ gap, const float* __restrict__ beap,
          float* __restrict__ out_t, float* __restrict__ out_a, int M)
{
    constexpr int F = 8, FA = 2;

    __shared__ float sh_w[512];
    __shared__ float sb0[F], sg0[F], sbe0[F];
    __shared__ float swa[16];
    __shared__ float sba[FA], sga[FA], sbea[FA];
    __shared__ float red[F * NW * 2];
    __shared__ float stA[F], stB[F];
    __shared__ float saA[FA], saB[FA];

    const int tid  = threadIdx.x;
    const int lane = tid & 31;
    const int warp = tid >> 5;
    const int m0   = blockIdx.x;

    for (int i = tid; i < 512; i += THREADS) sh_w[i] = Wp[(ll)m0 * 512 + i];
    if (tid < F) {
        sb0[tid]  = bp[m0 * 8 + tid];
        sg0[tid]  = gp[m0 * 8 + tid];
        sbe0[tid] = bep[m0 * 8 + tid];
    }
    if (tid < 16) swa[tid] = Wap[m0 * 16 + tid];
    if (tid < FA) {
        sba[tid]  = bap[m0 * 2 + tid];
        sga[tid]  = gap[m0 * 2 + tid];
        sbea[tid] = beap[m0 * 2 + tid];
    }
    __syncthreads();

    const float* xptr[RPT];
    #pragma unroll
    for (int r = 0; r < RPT; ++r)
        xptr[r] = xin + (ll)(tid + r * THREADS) * 65536 + (ll)m0 * 64;

    ull acc[RPT][4];
    #pragma unroll
    for (int r = 0; r < RPT; ++r)
        #pragma unroll
        for (int j = 0; j < 4; ++j) acc[r][j] = 0ull;

    #pragma unroll 1
    for (int c = 0; c < 16; ++c) {
        float xv[RPT][4];
        #pragma unroll
        for (int r = 0; r < RPT; ++r) {
            const float4 v = *reinterpret_cast<const float4*>(xptr[r] + c * 4);
            xv[r][0] = v.x; xv[r][1] = v.y; xv[r][2] = v.z; xv[r][3] = v.w;
        }
        #pragma unroll
        for (int dd = 0; dd < 4; ++dd) {
            ull w[4];
            #pragma unroll
            for (int p = 0; p < 4; ++p)
                w[p] = *reinterpret_cast<const ull*>(&sh_w[(c * 4 + dd) * 8 + 2 * p]);
            #pragma unroll
            for (int r = 0; r < RPT; ++r) {
                ull xx = pack2(xv[r][dd], xv[r][dd]);
                #pragma unroll
                for (int j = 0; j < 4; ++j) acc[r][j] = fma2(xx, w[j], acc[r][j]);
            }
        }
    }

    float tv[RPT][F];
    #pragma unroll
    for (int r = 0; r < RPT; ++r)
        #pragma unroll
        for (int p = 0; p < 4; ++p) {
            float lo, hi; unpack2(acc[r][p], lo, hi);
            int P = 2 * p;
            tv[r][P]     = ftanh(lo + sb0[P]);
            tv[r][P + 1] = ftanh(hi + sb0[P + 1]);
        }

    #pragma unroll
    for (int f = 0; f < F; ++f) {
        float s = 0.f, ss = 0.f;
        #pragma unroll
        for (int r = 0; r < RPT; ++r) { float v = tv[r][f]; s += v; ss += v * v; }
        #pragma unroll
        for (int o = 16; o; o >>= 1) {
            s  += __shfl_xor_sync(0xffffffffu, s, o);
            ss += __shfl_xor_sync(0xffffffffu, ss, o);
        }
        if (lane == 0) { red[f * NW + warp] = s; red[(F + f) * NW + warp] = ss; }
    }
    __syncthreads();
    if (tid < F) {
        int f = tid;
        float s = 0.f, ss = 0.f;
        #pragma unroll
        for (int w = 0; w < NW; ++w) { s += red[f * NW + w]; ss += red[(F + f) * NW + w]; }
        float mu  = s  * (1.f / B_ROWS);
        float var = ss * (1.f / B_ROWS) - mu * mu;
        float a   = sg0[f] * rsqrtf(var + BN_EPS);
        stA[f] = a;
        stB[f] = sbe0[f] - mu * a;
    }
    __syncthreads();

    float av[RPT][FA];
    #pragma unroll
    for (int r = 0; r < RPT; ++r) {
        int b = tid + r * THREADS;
        float tn[F];
        #pragma unroll
        for (int f = 0; f < F; ++f) tn[f] = fmaf(stA[f], tv[r][f], stB[f]);

        ll obase = ((ll)b * M + m0) * 8;
        #pragma unroll
        for (int q = 0; q < 2; ++q) {
            float4 v = make_float4(tn[q * 4], tn[q * 4 + 1], tn[q * 4 + 2], tn[q * 4 + 3]);
            *reinterpret_cast<float4*>(&out_t[obase + q * 4]) = v;
        }
        #pragma unroll
        for (int k = 0; k < 2; ++k) {
            float a = sba[k];
            #pragma unroll
            for (int h = 0; h < 8; ++h)
                a = fmaf(tn[h], swa[h * 2 + k], a);
            av[r][k] = ftanh(a);
        }
    }

    #pragma unroll
    for (int f = 0; f < FA; ++f) {
        float s = 0.f, ss = 0.f;
        #pragma unroll
        for (int r = 0; r < RPT; ++r) { float v = av[r][f]; s += v; ss += v * v; }
        #pragma unroll
        for (int o = 16; o; o >>= 1) {
            s  += __shfl_xor_sync(0xffffffffu, s, o);
            ss += __shfl_xor_sync(0xffffffffu, ss, o);
        }
        if (lane == 0) { red[f * NW + warp] = s; red[(FA + f) * NW + warp] = ss; }
    }
    __syncthreads();
    if (tid < FA) {
        int f = tid;
        float s = 0.f, ss = 0.f;
        #pragma unroll
        for (int w = 0; w < NW; ++w) { s += red[f * NW + w]; ss += red[(FA + f) * NW + w]; }
        float mu  = s  * (1.f / B_ROWS);
        float var = ss * (1.f / B_ROWS) - mu * mu;
        float a   = sga[f] * rsqrtf(var + BN_EPS);
        saA[f] = a;
        saB[f] = sbea[f] - mu * a;
    }
    __syncthreads();

    #pragma unroll
    for (int r = 0; r < RPT; ++r) {
        int b = tid + r * THREADS;
        ll obase = ((ll)b * M + m0) * 2;
        float2 v;
        v.x = fmaf(saA[0], av[r][0], saB[0]);
        v.y = fmaf(saA[1], av[r][1], saB[1]);
        *reinterpret_cast<float2*>(&out_a[obase]) = v;
    }
}

// Output layout: (aux0, aux1, t0, t1) flattened, fp32
static const ll OFF_A0 = 0;
static const ll OFF_A1 = 2048LL * 8192 * 2;            // 33,554,432
static const ll OFF_T0 = OFF_A1 + 2048LL * 1024 * 2;   // 37,748,736
static const ll OFF_T1 = OFF_T0 + 2048LL * 8192 * 8;   // 171,966,464

extern "C" void kernel_launch(void* const* d_in, const int* in_sizes, int n_in,
                              void* d_out, int out_size)
{
    const float* x    = (const float*)d_in[0];
    const float* W0   = (const float*)d_in[1];
    const float* b0   = (const float*)d_in[2];
    const float* g0   = (const float*)d_in[3];
    const float* be0  = (const float*)d_in[4];
    const float* Wa0  = (const float*)d_in[5];
    const float* ba0  = (const float*)d_in[6];
    const float* ga0  = (const float*)d_in[7];
    const float* bea0 = (const float*)d_in[8];
    const float* W1   = (const float*)d_in[9];
    const float* b1   = (const float*)d_in[10];
    const float* g1   = (const float*)d_in[11];
    const float* be1  = (const float*)d_in[12];
    const float* Wa1  = (const float*)d_in[13];
    const float* ba1  = (const float*)d_in[14];
    const float* ga1  = (const float*)d_in[15];
    const float* bea1 = (const float*)d_in[16];

    float* out  = (float*)d_out;
    float* aux0 = out + OFF_A0;
    float* aux1 = out + OFF_A1;
    float* t0   = out + OFF_T0;
    float* t1   = out + OFF_T1;

    // L0 dynamic smem: xT (16*2048) + weights/params/reduction scratch
    const int s0 = (16 * B_ROWS + 1024 + 16 * NW * 2 + 2 * 16 + 2 * 4
                    + 3 * 16 + 32 + 3 * 4) * 4;   // ~135 KB
    cudaFuncSetAttribute(reinterpret_cast<const void*>(l0_kernel),
                         cudaFuncAttributeMaxDynamicSharedMemorySize, s0);

    // Layer 0: 8192 terms, 2 per block; x L2-resident, staged transposed in smem
    l0_kernel<<<8192 / 2, THREADS, s0>>>(
        x, W0, b0, g0, be0, Wa0, ba0, ga0, bea0, t0, aux0, 8192);

    // Layer 1: 1024 roots; direct loads (best measured variant)
    l1_kernel<<<1024, THREADS>>>(
        t0, W1, b1, g1, be1, Wa1, ba1, ga1, bea1, t1, aux1, 1024);
}